// round 5
// baseline (speedup 1.0000x reference)
#include <cuda_runtime.h>
#include <cuda_bf16.h>
#include <math_constants.h>
#include <cstdint>

// Cross-entropy: mean over rows of (logsumexp(row) - row[target]).
// B=8192 rows, V=50257 cols, fp32 logits, int32 targets.
// One-pass online logsumexp, HBM-bound (~7.0 TB/s achieved at grid=8192).
// This version: PERSISTENT grid (148 SMs x 8 CTAs = 1184, single wave),
// each CTA loops over ~7 rows -> no wave transitions, DRAM queues stay full.
// Fused final mean via last-block-done ticket (wraps -> graph-replay safe).

#define B_ROWS   8192
#define V_COLS   50257
#define THREADS  256
#define GRID     1184              // 148 SMs * 8 CTAs/SM -> exactly one wave
#define L2E      1.4426950408889634f   // log2(e)
#define INV_L2E  0.6931471805599453f   // ln(2)

__device__ float g_row_loss[B_ROWS];
__device__ unsigned int g_ticket;      // zero-init; atomicInc wraps back to 0 each launch

__device__ __forceinline__ float ex2f(float x) {
    float y;
    asm("ex2.approx.ftz.f32 %0, %1;" : "=f"(y) : "f"(x));
    return y;
}

// Online update of (m, s) with element x, where s = sum_i 2^((x_i - m) * L2E).
// Single MUFU per element.
__device__ __forceinline__ void online_update(float x, float& m, float& s) {
    float d = x - m;
    float e = ex2f(-fabsf(d) * L2E);
    if (d > 0.0f) {
        s = fmaf(s, e, 1.0f);
        m = x;
    } else {
        s += e;
    }
}

__device__ __forceinline__ void online_merge(float mo, float so, float& m, float& s) {
    float M = fmaxf(m, mo);
    s = s * ex2f((m - M) * L2E) + so * ex2f((mo - M) * L2E);
    m = M;
}

__global__ __launch_bounds__(THREADS)
void ce_fused_kernel(const float* __restrict__ inp,
                     const int* __restrict__ tgt,
                     float* __restrict__ out) {
    __shared__ float sh_m[THREADS / 32];
    __shared__ float sh_s[THREADS / 32];
    __shared__ bool  sh_last;
    const int wid = threadIdx.x >> 5;
    const int lid = threadIdx.x & 31;

    // Persistent loop over rows.
    for (int row = blockIdx.x; row < B_ROWS; row += GRID) {
        const float* rowp = inp + (long long)row * V_COLS;

        // Alignment split: pre scalars -> 16B-aligned vec4 region -> tail.
        // (Row stride 50257*4B is only 4B-aligned.)
        const int mis  = (int)((((uintptr_t)rowp) >> 2) & 3);
        const int pre  = (4 - mis) & 3;
        const int nvec = (V_COLS - pre) >> 2;
        const int tail = V_COLS - pre - (nvec << 2);
        const float4* p4 = reinterpret_cast<const float4*>(rowp + pre);

        float m = -CUDART_INF_F;
        float s = 0.0f;

        if (threadIdx.x < pre) {
            online_update(__ldcs(rowp + threadIdx.x), m, s);
        }

        #pragma unroll 4
        for (int i = threadIdx.x; i < nvec; i += THREADS) {
            float4 v = __ldcs(p4 + i);
            online_update(v.x, m, s);
            online_update(v.y, m, s);
            online_update(v.z, m, s);
            online_update(v.w, m, s);
        }

        if (threadIdx.x < tail) {
            online_update(__ldcs(rowp + pre + (nvec << 2) + threadIdx.x), m, s);
        }

        // Warp reduction of (m, s).
        #pragma unroll
        for (int off = 16; off > 0; off >>= 1) {
            float mo = __shfl_xor_sync(0xffffffffu, m, off);
            float so = __shfl_xor_sync(0xffffffffu, s, off);
            online_merge(mo, so, m, s);
        }

        if (lid == 0) { sh_m[wid] = m; sh_s[wid] = s; }
        __syncthreads();

        if (threadIdx.x == 0) {
            m = sh_m[0]; s = sh_s[0];
            #pragma unroll
            for (int w = 1; w < THREADS / 32; ++w) {
                online_merge(sh_m[w], sh_s[w], m, s);
            }
            float lse = fmaf(__log2f(s), INV_L2E, m);   // m + ln(s)
            int t = tgt[row];
            t = min(max(t, 0), V_COLS - 1);
            float picked = __ldg(rowp + t);
            g_row_loss[row] = lse - picked;
        }
        __syncthreads();   // sh_m/sh_s reused next row iteration
    }

    // Last CTA to finish reduces all row losses (deterministic fixed order).
    if (threadIdx.x == 0) {
        __threadfence();
        unsigned int ticket = atomicInc(&g_ticket, (unsigned int)GRID - 1u);
        sh_last = (ticket == (unsigned int)GRID - 1u);
    }
    __syncthreads();

    if (sh_last) {
        float acc = 0.0f;
        for (int i = threadIdx.x; i < B_ROWS; i += THREADS) {
            acc += g_row_loss[i];
        }
        #pragma unroll
        for (int off = 16; off > 0; off >>= 1) {
            acc += __shfl_xor_sync(0xffffffffu, acc, off);
        }
        __shared__ float sh_acc[THREADS / 32];
        if (lid == 0) sh_acc[wid] = acc;
        __syncthreads();
        if (threadIdx.x == 0) {
            float total = sh_acc[0];
            #pragma unroll
            for (int w = 1; w < THREADS / 32; ++w) total += sh_acc[w];
            out[0] = total * (1.0f / (float)B_ROWS);
        }
    }
}

extern "C" void kernel_launch(void* const* d_in, const int* in_sizes, int n_in,
                              void* d_out, int out_size) {
    const float* inp = (const float*)d_in[0];
    const int* tgt = (const int*)d_in[1];
    float* out = (float*)d_out;

    ce_fused_kernel<<<GRID, THREADS>>>(inp, tgt, out);
}

// round 7
// speedup vs baseline: 1.0679x; 1.0679x over previous
#include <cuda_runtime.h>
#include <cuda_bf16.h>
#include <math_constants.h>
#include <cstdint>

// Cross-entropy: mean over rows of (logsumexp(row) - row[target]).
// B=8192 rows, V=50257 cols, fp32 logits, int32 targets.
// Main kernel: one CTA per row, one-pass online logsumexp, float4 __ldcs
// streaming with misalignment prologue (row stride 50257*4B is 4B-aligned).
// Proven 88% DRAM / 7.0 TB/s -> near HBM ceiling; left unchanged from R3.
// Final reduce: 1024 threads, vectorized loads, shallow tree (was the 4.9us
// serial-latency-chain kernel).

#define B_ROWS   8192
#define V_COLS   50257
#define THREADS  256
#define L2E      1.4426950408889634f   // log2(e)
#define INV_L2E  0.6931471805599453f   // ln(2)

__device__ float g_row_loss[B_ROWS];

__device__ __forceinline__ float ex2f(float x) {
    float y;
    asm("ex2.approx.ftz.f32 %0, %1;" : "=f"(y) : "f"(x));
    return y;
}

// Online update of (m, s) with element x, where s = sum_i 2^((x_i - m) * L2E).
// Single MUFU per element: e = 2^(-|x-m|*L2E), then predicated merge.
__device__ __forceinline__ void online_update(float x, float& m, float& s) {
    float d = x - m;
    float e = ex2f(-fabsf(d) * L2E);
    if (d > 0.0f) {          // new max: rescale old sum, add 1 for x itself
        s = fmaf(s, e, 1.0f);
        m = x;
    } else {                 // common case
        s += e;
    }
}

// Merge two (m, s) pairs.
__device__ __forceinline__ void online_merge(float mo, float so, float& m, float& s) {
    float M = fmaxf(m, mo);
    s = s * ex2f((m - M) * L2E) + so * ex2f((mo - M) * L2E);
    m = M;
}

__global__ __launch_bounds__(THREADS)
void ce_row_lse_kernel(const float* __restrict__ inp,
                       const int* __restrict__ tgt) {
    const int row = blockIdx.x;
    const float* rowp = inp + (long long)row * V_COLS;

    // Alignment split: pre scalars -> 16B-aligned vec4 region -> tail scalars.
    const int mis  = (int)((((uintptr_t)rowp) >> 2) & 3);   // misaligned floats
    const int pre  = (4 - mis) & 3;
    const int nvec = (V_COLS - pre) >> 2;
    const int tail = V_COLS - pre - (nvec << 2);
    const float4* p4 = reinterpret_cast<const float4*>(rowp + pre);

    float m = -CUDART_INF_F;
    float s = 0.0f;

    // Prologue scalars (0..3 elements).
    if (threadIdx.x < pre) {
        online_update(__ldcs(rowp + threadIdx.x), m, s);
    }

    // Vectorized streaming main loop.
    #pragma unroll 4
    for (int i = threadIdx.x; i < nvec; i += THREADS) {
        float4 v = __ldcs(p4 + i);
        online_update(v.x, m, s);
        online_update(v.y, m, s);
        online_update(v.z, m, s);
        online_update(v.w, m, s);
    }

    // Tail scalars (0..3 elements).
    if (threadIdx.x < tail) {
        online_update(__ldcs(rowp + pre + (nvec << 2) + threadIdx.x), m, s);
    }

    // Warp reduction of (m, s).
    #pragma unroll
    for (int off = 16; off > 0; off >>= 1) {
        float mo = __shfl_xor_sync(0xffffffffu, m, off);
        float so = __shfl_xor_sync(0xffffffffu, s, off);
        online_merge(mo, so, m, s);
    }

    // Cross-warp reduction via shared memory.
    __shared__ float sh_m[THREADS / 32];
    __shared__ float sh_s[THREADS / 32];
    const int wid = threadIdx.x >> 5;
    const int lid = threadIdx.x & 31;
    if (lid == 0) { sh_m[wid] = m; sh_s[wid] = s; }
    __syncthreads();

    if (threadIdx.x == 0) {
        m = sh_m[0]; s = sh_s[0];
        #pragma unroll
        for (int w = 1; w < THREADS / 32; ++w) {
            online_merge(sh_m[w], sh_s[w], m, s);
        }
        // lse (natural log) = m + ln(s) = m + log2(s) * ln(2)
        float lse = fmaf(__log2f(s), INV_L2E, m);
        int t = tgt[row];
        t = min(max(t, 0), V_COLS - 1);
        float picked = __ldg(rowp + t);
        g_row_loss[row] = lse - picked;
    }
}

// Fast final mean: 1024 threads, each reads 2 independent float4s (8192
// floats total = 1024 * 8), then shuffle+smem tree. Latency chain: 2
// parallel vector loads + ~15 reduce steps, vs 32 dependent scalar loads
// in the old version.
__global__ __launch_bounds__(1024)
void ce_final_reduce_kernel(float* __restrict__ out) {
    const float4* p4 = reinterpret_cast<const float4*>(g_row_loss);
    const int tid = threadIdx.x;

    float4 a = p4[tid];              // rows [4t, 4t+4)
    float4 b = p4[tid + 1024];       // rows [4096+4t, 4096+4t+4)
    float acc = (a.x + a.y) + (a.z + a.w) + (b.x + b.y) + (b.z + b.w);

    #pragma unroll
    for (int off = 16; off > 0; off >>= 1) {
        acc += __shfl_xor_sync(0xffffffffu, acc, off);
    }

    __shared__ float sh[32];
    const int wid = tid >> 5;
    const int lid = tid & 31;
    if (lid == 0) sh[wid] = acc;
    __syncthreads();

    if (wid == 0) {
        float v = sh[lid];
        #pragma unroll
        for (int off = 16; off > 0; off >>= 1) {
            v += __shfl_xor_sync(0xffffffffu, v, off);
        }
        if (lid == 0) {
            out[0] = v * (1.0f / (float)B_ROWS);
        }
    }
}

extern "C" void kernel_launch(void* const* d_in, const int* in_sizes, int n_in,
                              void* d_out, int out_size) {
    const float* inp = (const float*)d_in[0];
    const int* tgt = (const int*)d_in[1];
    float* out = (float*)d_out;

    ce_row_lse_kernel<<<B_ROWS, THREADS>>>(inp, tgt);
    ce_final_reduce_kernel<<<1, 1024>>>(out);
}